// round 8
// baseline (speedup 1.0000x reference)
#include <cuda_runtime.h>
#include <cstdint>
#include <cfloat>

// Shapes fixed by the problem: x is (64, 128, 4096) fp32.
#define NPOS   4096
#define NROWS  8192          // 64*128
#define TSTEP  248           // tile stride in floats (992 B: 32B-aligned for v8)
#define NTILES 17            // 16 tiles of 248 centers + right-aligned tail
#define NSTRIP 64            // 8192 rows / 128 rows-per-strip
#define RMAX   512           // gaussian radius cap (R=28 for width 3)

// Scratch in __device__ globals (no allocations allowed).
__device__ unsigned int g_part[NSTRIP * NPOS]; // per-strip packed counts
__device__ float        g_vec[NPOS];
__device__ int          g_min_bits;            // nonneg floats: int cmp == float cmp
__device__ int          g_max_bits;

// ---------------------------------------------------------------------------
// K1: count peaks/valleys per column position, per row-strip.
// 256-bit loads (ld.global.v8.b32, sm_103a; requires 32B-aligned addresses —
// hence TSTEP=248): warp owns a 256-float column tile (8 floats/lane),
// 16 rows. Masks (cmin/cmax) applied only at the flush.
// dd matches the reference exactly: (x[p+1]-x[p]) - (x[p]-x[p-1]).
// ---------------------------------------------------------------------------
__global__ __launch_bounds__(256) void k_counts(const float* __restrict__ x) {
    __shared__ unsigned int scol[256];

    const int lane = threadIdx.x & 31;
    const int warp = threadIdx.x >> 5;          // 0..7
    const int tile = blockIdx.x;                // 0..16
    const bool last = (tile == NTILES - 1);
    const int s    = last ? (NPOS - 256) : tile * TSTEP;   // tile loads [s, s+256)
    const int cmin = last ? (16 * TSTEP + 1) : (s + 1);    // centers owned:
    const int cmax = last ? (NPOS - 2)       : (s + TSTEP);//   [cmin, cmax]
    const int p0   = s + 8 * lane + 1;

    // Reset min/max scalars for this graph replay (runs before k_vec).
    if (tile == 0 && blockIdx.y == 0 && threadIdx.x == 0) {
        g_min_bits = 0x7F800000;   // +inf
        g_max_bits = 0;            // values are >= 0
    }

    scol[threadIdx.x] = 0u;
    __syncthreads();

    unsigned pk[8] = {0, 0, 0, 0, 0, 0, 0, 0};  // peak counts per center
    unsigned vl[8] = {0, 0, 0, 0, 0, 0, 0, 0};  // valley counts per center

    const int rowbase = blockIdx.y * 128 + warp * 16;
    const float* xb = x + (size_t)rowbase * NPOS + s + 8 * lane;

    #pragma unroll 4
    for (int k = 0; k < 16; k++) {
        unsigned r0, r1, r2, r3, r4, r5, r6, r7;
        asm volatile(
            "ld.global.v8.b32 {%0,%1,%2,%3,%4,%5,%6,%7}, [%8];"
            : "=r"(r0), "=r"(r1), "=r"(r2), "=r"(r3),
              "=r"(r4), "=r"(r5), "=r"(r6), "=r"(r7)
            : "l"(xb + (size_t)k * NPOS));

        // Seam: first two floats of the next lane (garbage in lane 31; its
        // dependent centers are always masked out at the flush).
        unsigned n0 = __shfl_down_sync(0xFFFFFFFFu, r0, 1);
        unsigned n1 = __shfl_down_sync(0xFFFFFFFFu, r1, 1);

        float f0 = __uint_as_float(r0), f1 = __uint_as_float(r1);
        float f2 = __uint_as_float(r2), f3 = __uint_as_float(r3);
        float f4 = __uint_as_float(r4), f5 = __uint_as_float(r5);
        float f6 = __uint_as_float(r6), f7 = __uint_as_float(r7);
        float f8 = __uint_as_float(n0), f9 = __uint_as_float(n1);

        float d0 = f1 - f0, d1 = f2 - f1, d2 = f3 - f2, d3 = f4 - f3;
        float d4 = f5 - f4, d5 = f6 - f5, d6 = f7 - f6, d7 = f8 - f7;
        float d8 = f9 - f8;

        float dd0 = d1 - d0, dd1 = d2 - d1, dd2 = d3 - d2, dd3 = d4 - d3;
        float dd4 = d5 - d4, dd5 = d6 - d5, dd6 = d7 - d6, dd7 = d8 - d7;

        pk[0] += (dd0 < 0.0f); vl[0] += (dd0 > 0.0f);
        pk[1] += (dd1 < 0.0f); vl[1] += (dd1 > 0.0f);
        pk[2] += (dd2 < 0.0f); vl[2] += (dd2 > 0.0f);
        pk[3] += (dd3 < 0.0f); vl[3] += (dd3 > 0.0f);
        pk[4] += (dd4 < 0.0f); vl[4] += (dd4 > 0.0f);
        pk[5] += (dd5 < 0.0f); vl[5] += (dd5 > 0.0f);
        pk[6] += (dd6 < 0.0f); vl[6] += (dd6 > 0.0f);
        pk[7] += (dd7 < 0.0f); vl[7] += (dd7 > 0.0f);
    }

    const int i0 = 8 * lane;                    // scol index of center p0
    #pragma unroll
    for (int i = 0; i < 8; i++) {
        const int p = p0 + i;
        if (p >= cmin && p <= cmax) {
            atomicAdd(&scol[i0 + i], pk[i] | (vl[i] << 16));
        }
    }
    __syncthreads();

    const int c = s + 1 + threadIdx.x;
    if (c >= cmin && c <= cmax) {
        g_part[blockIdx.y * NPOS + c] = scol[threadIdx.x];
    }
}

// ---------------------------------------------------------------------------
// K2: 32 blocks x 128 threads. Strip-sum -> gaussian conv -> min/max atomics.
// Gaussian tail beyond R = 9w+1 is < exp(-81): zero for fp32.
// ---------------------------------------------------------------------------
__global__ __launch_bounds__(128) void k_vec(const float* __restrict__ lpw,
                                             const float* __restrict__ lvw) {
    __shared__ unsigned int scnt[128 + 2 * RMAX];
    __shared__ float sgp[RMAX + 1];
    __shared__ float sgv[RMAX + 1];
    __shared__ float smn[4], smx[4];

    const int t = threadIdx.x;

    const float wp = expf(*lpw);
    const float wv = expf(*lvw);
    int R = (int)(9.0f * fmaxf(wp, wv)) + 1;
    if (R > RMAX) R = RMAX;

    for (int d = t; d <= R; d += 128) {
        float fd = (float)d;
        float tp = fd / wp;
        float tv = fd / wv;
        sgp[d] = expf(-tp * tp);
        sgv[d] = expf(-tv * tv);
    }

    const int pbase = blockIdx.x * 128;      // outputs [pbase, pbase+128)
    const int sbase = pbase - R;
    const int span  = 128 + 2 * R;
    for (int j = t; j < span; j += 128) {
        const int c = sbase + j;
        unsigned sum = 0;
        if (c >= 1 && c <= NPOS - 2) {
            #pragma unroll 8
            for (int k = 0; k < NSTRIP; k++) sum += g_part[k * NPOS + c];
        }
        scnt[j] = sum;
    }
    __syncthreads();

    const int ci = t + R;
    unsigned pk0 = scnt[ci];
    float acc = (float)(pk0 & 0xFFFFu) * sgp[0] + (float)(pk0 >> 16) * sgv[0];
    for (int d = 1; d <= R; d++) {
        unsigned pk = scnt[ci + d] + scnt[ci - d];
        acc += (float)(pk & 0xFFFFu) * sgp[d] + (float)(pk >> 16) * sgv[d];
    }
    g_vec[pbase + t] = acc;

    float mn = acc, mx = acc;
    #pragma unroll
    for (int o = 16; o > 0; o >>= 1) {
        mn = fminf(mn, __shfl_xor_sync(0xFFFFFFFFu, mn, o));
        mx = fmaxf(mx, __shfl_xor_sync(0xFFFFFFFFu, mx, o));
    }
    if ((t & 31) == 0) { smn[t >> 5] = mn; smx[t >> 5] = mx; }
    __syncthreads();
    if (t == 0) {
        mn = fminf(fminf(smn[0], smn[1]), fminf(smn[2], smn[3]));
        mx = fmaxf(fmaxf(smx[0], smx[1]), fmaxf(smx[2], smx[3]));
        atomicMin(&g_min_bits, __float_as_int(mn));  // nonneg floats
        atomicMax(&g_max_bits, __float_as_int(mx));
    }
}

// ---------------------------------------------------------------------------
// K3: normalize + broadcast (exact R4 version: plain float4 stores).
// ---------------------------------------------------------------------------
__global__ __launch_bounds__(1024) void k_bcast(float* __restrict__ out) {
    const int t = threadIdx.x;
    const float mn = __int_as_float(g_min_bits);
    const float inv = 1.0f / (__int_as_float(g_max_bits) - mn + 1e-6f);

    float4 v = ((const float4*)g_vec)[t];
    v.x = (v.x - mn) * inv;
    v.y = (v.y - mn) * inv;
    v.z = (v.z - mn) * inv;
    v.w = (v.w - mn) * inv;

    float4* o = (float4*)out + (size_t)blockIdx.x * 16 * 1024 + t;
    #pragma unroll
    for (int r = 0; r < 16; r++) {
        o[(size_t)r * 1024] = v;
    }
}

// ---------------------------------------------------------------------------
extern "C" void kernel_launch(void* const* d_in, const int* in_sizes, int n_in,
                              void* d_out, int out_size) {
    const float* x   = (const float*)d_in[0];
    const float* lpw = (const float*)d_in[1];
    const float* lvw = (const float*)d_in[2];
    float* out = (float*)d_out;

    k_counts<<<dim3(NTILES, NSTRIP), 256>>>(x);
    k_vec<<<NPOS / 128, 128>>>(lpw, lvw);
    k_bcast<<<NROWS / 16, 1024>>>(out);
}